// round 1
// baseline (speedup 1.0000x reference)
#include <cuda_runtime.h>
#include <cuda_bf16.h>

// PMF rating prediction: out[p] = relu(dot(user_emb[user_ids[p]], item_emb[item_ids[p]]))
// D = 64 floats = 256 bytes per row.
//
// Strategy: 16 lanes per pair. Each lane loads one float4 from the user row and
// one float4 from the item row (16 * 16B = 256B, two coalesced 128B lines),
// accumulates 4 products, then a 4-step shfl_xor reduction over the 16-lane
// group. 256-thread blocks handle 16 pairs each.

#define HIDDEN 64
#define LANES_PER_PAIR 16
#define THREADS 256
#define PAIRS_PER_BLOCK (THREADS / LANES_PER_PAIR)

__global__ __launch_bounds__(THREADS)
void pmf_kernel(const float* __restrict__ user_emb,
                const float* __restrict__ item_emb,
                const int*   __restrict__ user_ids,
                const int*   __restrict__ item_ids,
                float*       __restrict__ out,
                int num_pairs)
{
    int group = threadIdx.x >> 4;          // 0..15 within block
    int lane  = threadIdx.x & 15;          // 0..15 within group
    long long p = (long long)blockIdx.x * PAIRS_PER_BLOCK + group;
    if (p >= num_pairs) return;

    int uid = __ldg(&user_ids[p]);
    int iid = __ldg(&item_ids[p]);

    const float4* urow = reinterpret_cast<const float4*>(user_emb + (long long)uid * HIDDEN);
    const float4* irow = reinterpret_cast<const float4*>(item_emb + (long long)iid * HIDDEN);

    float4 u = __ldg(&urow[lane]);
    float4 v = __ldg(&irow[lane]);

    float acc = u.x * v.x + u.y * v.y + u.z * v.z + u.w * v.w;

    // Reduce over 16 lanes (stays within the 16-lane group under xor masks < 16)
    acc += __shfl_xor_sync(0xFFFFFFFFu, acc, 8);
    acc += __shfl_xor_sync(0xFFFFFFFFu, acc, 4);
    acc += __shfl_xor_sync(0xFFFFFFFFu, acc, 2);
    acc += __shfl_xor_sync(0xFFFFFFFFu, acc, 1);

    if (lane == 0)
        out[p] = fmaxf(acc, 0.0f);
}

extern "C" void kernel_launch(void* const* d_in, const int* in_sizes, int n_in,
                              void* d_out, int out_size)
{
    const float* user_emb = (const float*)d_in[0];
    const float* item_emb = (const float*)d_in[1];
    const int*   user_ids = (const int*)d_in[2];
    const int*   item_ids = (const int*)d_in[3];
    float*       out      = (float*)d_out;

    int num_pairs = in_sizes[2];  // 2,000,000
    int blocks = (num_pairs + PAIRS_PER_BLOCK - 1) / PAIRS_PER_BLOCK;

    pmf_kernel<<<blocks, THREADS>>>(user_emb, item_emb, user_ids, item_ids,
                                    out, num_pairs);
}

// round 2
// speedup vs baseline: 1.3896x; 1.3896x over previous
#include <cuda_runtime.h>
#include <cuda_bf16.h>

// PMF: out[p] = relu(dot(user_emb[user_ids[p]], item_emb[item_ids[p]])), D=64 fp32.
//
// R2: latency-bound fix. 16 lanes per pair (one float4 per lane per row, two
// coalesced 128B lines per 256B row). Each group batches PB=4 pairs:
//   phase 1: load 8 ids (independent)
//   phase 2: issue all 8 float4 row loads back-to-back (MLP=8/thread)
//   phase 3: dot + 16-lane shfl reduction + store
// Pairs are interleaved (group + 16*k) so id loads and stores stay coalesced.

#define HIDDEN 64
#define THREADS 256
#define GROUPS_PER_BLOCK (THREADS / 16)   // 16
#define PB 4                               // pairs per group
#define PAIRS_PER_BLOCK (GROUPS_PER_BLOCK * PB)  // 64

__global__ __launch_bounds__(THREADS)
void pmf_kernel(const float* __restrict__ user_emb,
                const float* __restrict__ item_emb,
                const int*   __restrict__ user_ids,
                const int*   __restrict__ item_ids,
                float*       __restrict__ out,
                int num_pairs)
{
    const int group = threadIdx.x >> 4;    // 0..15
    const int lane  = threadIdx.x & 15;    // 0..15
    const long long base = (long long)blockIdx.x * PAIRS_PER_BLOCK;

    long long p[PB];
    int uid[PB], iid[PB];
    bool valid[PB];

    // Phase 1: all id loads, independent, front-batched.
    #pragma unroll
    for (int k = 0; k < PB; k++) {
        p[k] = base + (long long)k * GROUPS_PER_BLOCK + group;
        valid[k] = (p[k] < num_pairs);
        long long q = valid[k] ? p[k] : 0;
        uid[k] = __ldg(&user_ids[q]);
        iid[k] = __ldg(&item_ids[q]);
    }

    // Phase 2: all row loads, independent, front-batched (MLP = 8).
    float4 u[PB], v[PB];
    #pragma unroll
    for (int k = 0; k < PB; k++) {
        const float4* urow = reinterpret_cast<const float4*>(
            user_emb + (long long)uid[k] * HIDDEN);
        const float4* irow = reinterpret_cast<const float4*>(
            item_emb + (long long)iid[k] * HIDDEN);
        u[k] = __ldg(&urow[lane]);
        v[k] = __ldg(&irow[lane]);
    }

    // Phase 3: dot products, 16-lane reductions, stores.
    #pragma unroll
    for (int k = 0; k < PB; k++) {
        float acc = u[k].x * v[k].x + u[k].y * v[k].y
                  + u[k].z * v[k].z + u[k].w * v[k].w;
        acc += __shfl_xor_sync(0xFFFFFFFFu, acc, 8);
        acc += __shfl_xor_sync(0xFFFFFFFFu, acc, 4);
        acc += __shfl_xor_sync(0xFFFFFFFFu, acc, 2);
        acc += __shfl_xor_sync(0xFFFFFFFFu, acc, 1);
        if (lane == 0 && valid[k])
            out[p[k]] = fmaxf(acc, 0.0f);
    }
}

extern "C" void kernel_launch(void* const* d_in, const int* in_sizes, int n_in,
                              void* d_out, int out_size)
{
    const float* user_emb = (const float*)d_in[0];
    const float* item_emb = (const float*)d_in[1];
    const int*   user_ids = (const int*)d_in[2];
    const int*   item_ids = (const int*)d_in[3];
    float*       out      = (float*)d_out;

    int num_pairs = in_sizes[2];
    int blocks = (num_pairs + PAIRS_PER_BLOCK - 1) / PAIRS_PER_BLOCK;

    pmf_kernel<<<blocks, THREADS>>>(user_emb, item_emb, user_ids, item_ids,
                                    out, num_pairs);
}